// round 15
// baseline (speedup 1.0000x reference)
#include <cuda_runtime.h>
#include <cuda_bf16.h>
#include <cstdint>

// Problem constants
#define B_   8
#define LQ_  512
#define LK_  512
#define D_   512
#define H_   128
#define M_   (B_ * LQ_)   // 4096 rows per projection

#define NTANH 64   // h in [0,64): MUFU tanh path (packed pairs)
#define NEXP  64   // h in [64,128): exp-product + fma-pipe reciprocal path

// Scratch (no cudaMalloc allowed)
__device__ float g_Q[M_ * H_];    // raw projections (cols [0,64) used)
__device__ float g_K[M_ * H_];
__device__ float g_EQ[M_ * H_];   // e^{2q} (cols [64,128) used)
__device__ float g_EK[M_ * H_];

__device__ __forceinline__ float fast_tanh(float x) {
    float y;
    asm("tanh.approx.f32 %0, %1;" : "=f"(y) : "f"(x));
    return y;
}
__device__ __forceinline__ float fast_ex2(float x) {
    float y;
    asm("ex2.approx.f32 %0, %1;" : "=f"(y) : "f"(x));
    return y;
}

typedef unsigned long long ull;
__device__ __forceinline__ ull fma2_(ull a, ull b, ull c) {
    ull d; asm("fma.rn.f32x2 %0, %1, %2, %3;" : "=l"(d) : "l"(a), "l"(b), "l"(c)); return d;
}
__device__ __forceinline__ ull mul2_(ull a, ull b) {
    ull d; asm("mul.rn.f32x2 %0, %1, %2;" : "=l"(d) : "l"(a), "l"(b)); return d;
}
__device__ __forceinline__ ull add2_(ull a, ull b) {
    ull d; asm("add.rn.f32x2 %0, %1, %2;" : "=l"(d) : "l"(a), "l"(b)); return d;
}
__device__ __forceinline__ ull pack2(float lo, float hi) {
    ull p; asm("mov.b64 %0, {%1, %2};" : "=l"(p) : "f"(lo), "f"(hi)); return p;
}
__device__ __forceinline__ void unpack2(ull p, float& lo, float& hi) {
    asm("mov.b64 {%0, %1}, %2;" : "=f"(lo), "=f"(hi) : "l"(p));
}

// ---------------------------------------------------------------------------
// Projection GEMM, double-buffered pipeline.
// BM=64, BK=32, BN=128, 512 threads, 128 blocks (1/SM).
// Per iter (16 total): prefetch gmem (c+1) -> compute buf[c&1] ->
// store prefetched into buf[(c+1)&1] -> ONE sync. Critical path ~ fma floor.
// Epilogue: cols < 64 -> store raw Y; cols >= 64 -> store E = exp(2y).
// ---------------------------------------------------------------------------
#define BM 64
#define BK 32
#define BN 128
#define ASTR 72                     // As row stride (transposed [BK][BM+8])
#define P_ASZ (BK * ASTR)           // 2304 floats per A buffer
#define P_BSZ (BK * BN)             // 4096 floats per B buffer
#define P_SMEM_FLOATS (2 * P_ASZ + 2 * P_BSZ)   // 12800 -> 51200 bytes

__global__ __launch_bounds__(512) void proj_kernel(
    const float* __restrict__ qs, const float* __restrict__ ks,
    const float* __restrict__ Wq, const float* __restrict__ Wk)
{
    extern __shared__ float psm[];
    float* Abuf[2] = {psm, psm + P_ASZ};
    float* Bbuf[2] = {psm + 2 * P_ASZ, psm + 2 * P_ASZ + P_BSZ};

    const int nb = M_ / BM;                 // 64 blocks per projection
    bool isK = (blockIdx.x >= nb);
    int bm = isK ? (blockIdx.x - nb) : blockIdx.x;
    const float* __restrict__ X = isK ? ks : qs;
    const float* __restrict__ W = isK ? Wk : Wq;
    float* __restrict__ Y = isK ? g_K : g_Q;
    float* __restrict__ E = isK ? g_EK : g_EQ;

    int tid = threadIdx.x;
    int tx = tid & 31;               // col group: cols tx*4 .. +3
    int ty = tid >> 5;               // row group: rows ty*4 .. +3 (16 groups)

    // A tile 64x32 = 512 float4: one per thread
    int ar  = tid >> 3;              // row 0..63
    int ac4 = tid & 7;               // k-col group 0..7
    // B tile 32x128 = 1024 float4: two per thread (rows br, br+16)
    int br  = tid >> 5;              // k-row 0..15
    int bc4 = tid & 31;

    const float* Xp = X + (size_t)(bm * BM + ar) * D_ + ac4 * 4;
    const float* Wp = W + (size_t)br * BN + bc4 * 4;

    ull acc2[2][4];                  // [row pair i][col j]
#pragma unroll
    for (int i = 0; i < 2; i++)
#pragma unroll
        for (int j = 0; j < 4; j++) acc2[i][j] = 0ull;

    // Prologue: load + stage iter 0
    float4 pa  = *(const float4*)(Xp);
    float4 pb0 = *(const float4*)(Wp);
    float4 pb1 = *(const float4*)(Wp + (size_t)16 * BN);
    {
        float* A0 = Abuf[0];
        A0[(ac4 * 4 + 0) * ASTR + ar] = pa.x;
        A0[(ac4 * 4 + 1) * ASTR + ar] = pa.y;
        A0[(ac4 * 4 + 2) * ASTR + ar] = pa.z;
        A0[(ac4 * 4 + 3) * ASTR + ar] = pa.w;
        *(float4*)(&Bbuf[0][br * BN + bc4 * 4])        = pb0;
        *(float4*)(&Bbuf[0][(br + 16) * BN + bc4 * 4]) = pb1;
    }
    __syncthreads();

    const int NITER = D_ / BK;       // 16
    for (int c = 0; c < NITER; ++c) {
        int nx = c + 1;
        if (nx < NITER) {            // prefetch next tiles (hidden by compute)
            pa  = *(const float4*)(Xp + nx * BK);
            pb0 = *(const float4*)(Wp + (size_t)(nx * BK) * BN);
            pb1 = *(const float4*)(Wp + (size_t)(nx * BK + 16) * BN);
        }

        const float* Ac = Abuf[c & 1];
        const float* Bc = Bbuf[c & 1];
#pragma unroll
        for (int kk = 0; kk < BK; ++kk) {
            ulonglong2 a01 = *(const ulonglong2*)(&Ac[kk * ASTR + ty * 4]);
            ull ap[2] = {a01.x, a01.y};
            float4 bv = *(const float4*)(&Bc[kk * BN + tx * 4]);
            ull bd[4] = {pack2(bv.x, bv.x), pack2(bv.y, bv.y),
                         pack2(bv.z, bv.z), pack2(bv.w, bv.w)};
#pragma unroll
            for (int i = 0; i < 2; i++)
#pragma unroll
                for (int j = 0; j < 4; j++)
                    acc2[i][j] = fma2_(ap[i], bd[j], acc2[i][j]);
        }

        if (nx < NITER) {            // stage prefetched into the idle buffer
            float* An = Abuf[nx & 1];
            An[(ac4 * 4 + 0) * ASTR + ar] = pa.x;
            An[(ac4 * 4 + 1) * ASTR + ar] = pa.y;
            An[(ac4 * 4 + 2) * ASTR + ar] = pa.z;
            An[(ac4 * 4 + 3) * ASTR + ar] = pa.w;
            *(float4*)(&Bbuf[nx & 1][br * BN + bc4 * 4])        = pb0;
            *(float4*)(&Bbuf[nx & 1][(br + 16) * BN + bc4 * 4]) = pb1;
        }
        __syncthreads();
    }

    // Epilogue: rows (ty*4+2i, +1) in (lo, hi); cols tx*4..+3.
    // cols < 64 (tx < 16): raw Y only.  cols >= 64: E = exp(2y) only.
    const float LOG2E2 = 2.8853900817779268f;   // 2*log2(e)
#pragma unroll
    for (int i = 0; i < 2; i++) {
        float lo[4], hi[4];
#pragma unroll
        for (int j = 0; j < 4; j++) unpack2(acc2[i][j], lo[j], hi[j]);
        size_t r0 = (size_t)(bm * BM + ty * 4 + 2 * i) * H_ + tx * 4;
        if (tx < 16) {
            *(float4*)(Y + r0)      = make_float4(lo[0], lo[1], lo[2], lo[3]);
            *(float4*)(Y + r0 + H_) = make_float4(hi[0], hi[1], hi[2], hi[3]);
        } else {
            float4 el = make_float4(
                fast_ex2(lo[0] * LOG2E2), fast_ex2(lo[1] * LOG2E2),
                fast_ex2(lo[2] * LOG2E2), fast_ex2(lo[3] * LOG2E2));
            float4 eh = make_float4(
                fast_ex2(hi[0] * LOG2E2), fast_ex2(hi[1] * LOG2E2),
                fast_ex2(hi[2] * LOG2E2), fast_ex2(hi[3] * LOG2E2));
            *(float4*)(E + r0)      = el;
            *(float4*)(E + r0 + H_) = eh;
        }
    }
}

// ---------------------------------------------------------------------------
// Score kernel (R12, equal-best 55.9us): 64/64 dual-pipe, interleaved.
// ---------------------------------------------------------------------------
#define TQ 32
#define TK 64
#define SR 66
#define OFF_QR 0
#define OFF_KR (OFF_QR + TQ * SR)
#define OFF_QE (OFF_KR + TK * SR)
#define OFF_KE (OFF_QE + TQ * SR)
#define OFF_WV (OFF_KE + TK * SR)
#define SMEM_FLOATS (OFF_WV + H_)          // 12800 -> 51200 bytes

__global__ __launch_bounds__(256) void score_kernel(
    const float* __restrict__ wv, float* __restrict__ out)
{
    extern __shared__ float sm[];
    float* qr  = sm + OFF_QR;
    float* kr  = sm + OFF_KR;
    float* qe  = sm + OFF_QE;
    float* ke  = sm + OFF_KE;
    float* swv = sm + OFF_WV;

    int b  = blockIdx.z;
    int q0 = blockIdx.y * TQ;
    int k0 = blockIdx.x * TK;

    int tid = threadIdx.x;
    int tx = tid & 15;
    int ty = tid >> 4;

    if (tid < H_) swv[tid] = wv[tid];

    const size_t qoff = (size_t)(b * LQ_ + q0) * H_;
    const size_t koff = (size_t)(b * LK_ + k0) * H_;

    for (int i = tid; i < TQ * 16; i += 256) {
        int r = i >> 4, c = i & 15;
        float4 v = *(const float4*)(g_Q + qoff + r * H_ + c * 4);
        float* d = &qr[r * SR + c * 4];
        *(float2*)(d)     = make_float2(v.x, v.y);
        *(float2*)(d + 2) = make_float2(v.z, v.w);
        float4 e = *(const float4*)(g_EQ + qoff + r * H_ + NTANH + c * 4);
        float* de = &qe[r * SR + c * 4];
        *(float2*)(de)     = make_float2(e.x, e.y);
        *(float2*)(de + 2) = make_float2(e.z, e.w);
    }
    for (int i = tid; i < TK * 16; i += 256) {
        int r = i >> 4, c = i & 15;
        float4 v = *(const float4*)(g_K + koff + r * H_ + c * 4);
        float* d = &kr[r * SR + c * 4];
        *(float2*)(d)     = make_float2(v.x, v.y);
        *(float2*)(d + 2) = make_float2(v.z, v.w);
        float4 e = *(const float4*)(g_EK + koff + r * H_ + NTANH + c * 4);
        float* de = &ke[r * SR + c * 4];
        *(float2*)(de)     = make_float2(e.x, e.y);
        *(float2*)(de + 2) = make_float2(e.z, e.w);
    }
    __syncthreads();

    ull accA[2][4];
    ull accB[2][4];
#pragma unroll
    for (int i = 0; i < 2; i++)
#pragma unroll
        for (int j = 0; j < 4; j++) { accA[i][j] = 0ull; accB[i][j] = 0ull; }

    const ull TWO2 = pack2(2.0f, 2.0f);
    const ull ONE2 = pack2(1.0f, 1.0f);
    const float* qr0 = qr + ty * SR;
    const float* kr0 = kr + tx * SR;
    const float* qe0 = qe + ty * SR;
    const float* ke0 = ke + tx * SR;

    for (int it = 0; it < 8; ++it) {
#pragma unroll
        for (int pp = 0; pp < 4; ++pp) {
            int p = it * 4 + pp;
            ull w2 = *(const ull*)(&swv[2 * p]);
            ull q2[2], k2[4];
            q2[0] = *(const ull*)(&qr0[2 * p]);
            q2[1] = *(const ull*)(&qr0[16 * SR + 2 * p]);
            k2[0] = *(const ull*)(&kr0[2 * p]);
            k2[1] = *(const ull*)(&kr0[16 * SR + 2 * p]);
            k2[2] = *(const ull*)(&kr0[32 * SR + 2 * p]);
            k2[3] = *(const ull*)(&kr0[48 * SR + 2 * p]);
#pragma unroll
            for (int i = 0; i < 2; i++)
#pragma unroll
                for (int j = 0; j < 4; j++) {
                    ull s = add2_(q2[i], k2[j]);
                    float sx, sy;
                    unpack2(s, sx, sy);
                    ull t = pack2(fast_tanh(sx), fast_tanh(sy));
                    accA[i][j] = fma2_(w2, t, accA[i][j]);
                }
        }
#pragma unroll
        for (int pp = 0; pp < 4; ++pp) {
            int p = it * 4 + pp;
            ull w2 = *(const ull*)(&swv[NTANH + 2 * p]);
            ull Eq2[2], Ek2[4];
            Eq2[0] = *(const ull*)(&qe0[2 * p]);
            Eq2[1] = *(const ull*)(&qe0[16 * SR + 2 * p]);
            Ek2[0] = *(const ull*)(&ke0[2 * p]);
            Ek2[1] = *(const ull*)(&ke0[16 * SR + 2 * p]);
            Ek2[2] = *(const ull*)(&ke0[32 * SR + 2 * p]);
            Ek2[3] = *(const ull*)(&ke0[48 * SR + 2 * p]);
#pragma unroll
            for (int i = 0; i < 2; i++)
#pragma unroll
                for (int j = 0; j < 4; j++) {
                    ull d = fma2_(Eq2[i], Ek2[j], ONE2);
                    float dx, dy;
                    unpack2(d, dx, dy);
                    float mx = __uint_as_float(0xFEF311C3u - __float_as_uint(dx));
                    float my = __uint_as_float(0xFEF311C3u - __float_as_uint(dy));
                    ull m = pack2(mx, my);
                    ull u = fma2_(d, m, TWO2);
                    m = mul2_(m, u);
                    u = fma2_(d, m, TWO2);
                    m = mul2_(m, u);
                    accB[i][j] = fma2_(w2, m, accB[i][j]);
                }
        }
    }

    float ws = 0.f;
#pragma unroll
    for (int h = NTANH; h < H_; ++h) ws += swv[h];

    float* ob = out + ((size_t)b * LQ_ + q0) * LK_ + k0;
#pragma unroll
    for (int i = 0; i < 2; i++)
#pragma unroll
        for (int j = 0; j < 4; j++) {
            float ax, ay, bx, by;
            unpack2(accA[i][j], ax, ay);
            unpack2(accB[i][j], bx, by);
            float val = (ax + ay) + ws + 2.0f * (bx + by);
            ob[(size_t)(ty + 16 * i) * LK_ + tx + 16 * j] = val;
        }
}

// ---------------------------------------------------------------------------

extern "C" void kernel_launch(void* const* d_in, const int* in_sizes, int n_in,
                              void* d_out, int out_size)
{
    const float* qs = (const float*)d_in[0];   // [8,512,512]
    const float* ks = (const float*)d_in[1];   // [8,512,512]
    const float* Wq = (const float*)d_in[2];   // [512,128]
    const float* Wk = (const float*)d_in[3];   // [512,128]
    const float* wv = (const float*)d_in[4];   // [128]
    float* out = (float*)d_out;                // [8,512,512]

    static int attr_set = 0;
    if (!attr_set) {
        cudaFuncSetAttribute(proj_kernel,
                             cudaFuncAttributeMaxDynamicSharedMemorySize,
                             P_SMEM_FLOATS * sizeof(float));
        cudaFuncSetAttribute(score_kernel,
                             cudaFuncAttributeMaxDynamicSharedMemorySize,
                             SMEM_FLOATS * sizeof(float));
        attr_set = 1;
    }

    proj_kernel<<<2 * (M_ / BM), 512, P_SMEM_FLOATS * sizeof(float)>>>(
        qs, ks, Wq, Wk);

    dim3 grid(LK_ / TK, LQ_ / TQ, B_);
    score_kernel<<<grid, 256, SMEM_FLOATS * sizeof(float)>>>(wv, out);
}

// round 16
// speedup vs baseline: 1.1533x; 1.1533x over previous
#include <cuda_runtime.h>
#include <cuda_bf16.h>
#include <cstdint>

// Problem constants
#define B_   8
#define LQ_  512
#define LK_  512
#define D_   512
#define H_   128
#define M_   (B_ * LQ_)   // 4096 rows per projection

#define NTANH 64   // h in [0,64): MUFU tanh path
#define NEXP  64   // h in [64,128): exp-product + fma-pipe reciprocal path

// Scratch (no cudaMalloc allowed)
__device__ float g_Q[M_ * H_];    // raw projections (cols [0,64) used by score)
__device__ float g_K[M_ * H_];
__device__ float g_EQ[M_ * H_];   // e^{2q} (cols [64,128) used by score)
__device__ float g_EK[M_ * H_];

__device__ __forceinline__ float fast_tanh(float x) {
    float y;
    asm("tanh.approx.f32 %0, %1;" : "=f"(y) : "f"(x));
    return y;
}
__device__ __forceinline__ float fast_ex2(float x) {
    float y;
    asm("ex2.approx.f32 %0, %1;" : "=f"(y) : "f"(x));
    return y;
}

typedef unsigned long long ull;
__device__ __forceinline__ ull fma2_(ull a, ull b, ull c) {
    ull d; asm("fma.rn.f32x2 %0, %1, %2, %3;" : "=l"(d) : "l"(a), "l"(b), "l"(c)); return d;
}
__device__ __forceinline__ ull mul2_(ull a, ull b) {
    ull d; asm("mul.rn.f32x2 %0, %1, %2;" : "=l"(d) : "l"(a), "l"(b)); return d;
}
__device__ __forceinline__ ull add2_(ull a, ull b) {
    ull d; asm("add.rn.f32x2 %0, %1, %2;" : "=l"(d) : "l"(a), "l"(b)); return d;
}
__device__ __forceinline__ ull pack2(float lo, float hi) {
    ull p; asm("mov.b64 %0, {%1, %2};" : "=l"(p) : "f"(lo), "f"(hi)); return p;
}
__device__ __forceinline__ void unpack2(ull p, float& lo, float& hi) {
    asm("mov.b64 {%0, %1}, %2;" : "=f"(lo), "=f"(hi) : "l"(p));
}

// ---------------------------------------------------------------------------
// Projection GEMM: R10 base (256 thr, BM=64, BK=16, BN=128, 128 blocks,
// FFMA2 inner) + ping-pong double buffer via INTEGER OFFSETS:
// one __syncthreads per iter; stage(c+1) writes the idle buffer while
// compute(c) reads the active one. Epilogue halved: cols<64 -> raw Y,
// cols>=64 -> E = exp(2y).
// ---------------------------------------------------------------------------
#define BM 64
#define BK 16
#define BN 128
#define ASTR 72                     // As row stride (transposed [BK][BM+8])
#define P_ASZ (BK * ASTR)           // 1152 floats per A buffer
#define P_BSZ (BK * BN)             // 2048 floats per B buffer
#define P_SMEM_FLOATS (2 * P_ASZ + 2 * P_BSZ)   // 6400 -> 25600 bytes

__global__ __launch_bounds__(256) void proj_kernel(
    const float* __restrict__ qs, const float* __restrict__ ks,
    const float* __restrict__ Wq, const float* __restrict__ Wk)
{
    extern __shared__ float psm[];
    // layout: A0 | A1 | B0 | B1

    const int nb = M_ / BM;                 // 64 blocks per projection
    bool isK = (blockIdx.x >= nb);
    int bm = isK ? (blockIdx.x - nb) : blockIdx.x;
    const float* __restrict__ X = isK ? ks : qs;
    const float* __restrict__ W = isK ? Wk : Wq;
    float* __restrict__ Y = isK ? g_K : g_Q;
    float* __restrict__ E = isK ? g_EK : g_EQ;

    int tid = threadIdx.x;
    int tx = tid & 31;               // col group: cols tx*4 .. +3
    int ty = tid >> 5;               // row group: rows ty*8 .. +7
    int ar  = tid >> 2, ac4 = tid & 3;     // A tile 64x16 = 256 float4, 1/thr
    int br  = tid >> 5, bc4 = tid & 31;    // B tile 16x128: rows br, br+8

    const float* Xp  = X + (size_t)(bm * BM + ar) * D_ + ac4 * 4;
    const float* Wp0 = W + (size_t)br * BN + bc4 * 4;
    const float* Wp1 = W + (size_t)(br + 8) * BN + bc4 * 4;

    ull acc2[4][4];
#pragma unroll
    for (int i = 0; i < 4; i++)
#pragma unroll
        for (int j = 0; j < 4; j++) acc2[i][j] = 0ull;

    // Prologue: load + stage iter 0 into buffer 0
    float4 pa  = *(const float4*)(Xp);
    float4 pb0 = *(const float4*)(Wp0);
    float4 pb1 = *(const float4*)(Wp1);
    {
        float* A0 = psm;
        float* B0 = psm + 2 * P_ASZ;
        A0[(ac4 * 4 + 0) * ASTR + ar] = pa.x;
        A0[(ac4 * 4 + 1) * ASTR + ar] = pa.y;
        A0[(ac4 * 4 + 2) * ASTR + ar] = pa.z;
        A0[(ac4 * 4 + 3) * ASTR + ar] = pa.w;
        *(float4*)(&B0[br * BN + bc4 * 4])       = pb0;
        *(float4*)(&B0[(br + 8) * BN + bc4 * 4]) = pb1;
    }
    __syncthreads();

    const int NITER = D_ / BK;       // 32
    for (int c = 0; c < NITER; ++c) {
        int nx = c + 1;
        if (nx < NITER) {            // gmem prefetch, hidden under compute
            pa  = *(const float4*)(Xp + nx * BK);
            pb0 = *(const float4*)(Wp0 + (size_t)(nx * BK) * BN);
            pb1 = *(const float4*)(Wp1 + (size_t)(nx * BK) * BN);
        }

        const float* Ac = psm + (c & 1) * P_ASZ;
        const float* Bc = psm + 2 * P_ASZ + (c & 1) * P_BSZ;
#pragma unroll
        for (int kk = 0; kk < BK; ++kk) {
            ulonglong2 a01 = *(const ulonglong2*)(&Ac[kk * ASTR + ty * 8]);
            ulonglong2 a23 = *(const ulonglong2*)(&Ac[kk * ASTR + ty * 8 + 4]);
            ull ap[4] = {a01.x, a01.y, a23.x, a23.y};
            float4 bv = *(const float4*)(&Bc[kk * BN + tx * 4]);
            ull bd[4] = {pack2(bv.x, bv.x), pack2(bv.y, bv.y),
                         pack2(bv.z, bv.z), pack2(bv.w, bv.w)};
#pragma unroll
            for (int i = 0; i < 4; i++)
#pragma unroll
                for (int j = 0; j < 4; j++)
                    acc2[i][j] = fma2_(ap[i], bd[j], acc2[i][j]);
        }

        if (nx < NITER) {            // stage into the idle buffer
            float* An = psm + (nx & 1) * P_ASZ;
            float* Bn = psm + 2 * P_ASZ + (nx & 1) * P_BSZ;
            An[(ac4 * 4 + 0) * ASTR + ar] = pa.x;
            An[(ac4 * 4 + 1) * ASTR + ar] = pa.y;
            An[(ac4 * 4 + 2) * ASTR + ar] = pa.z;
            An[(ac4 * 4 + 3) * ASTR + ar] = pa.w;
            *(float4*)(&Bn[br * BN + bc4 * 4])       = pb0;
            *(float4*)(&Bn[(br + 8) * BN + bc4 * 4]) = pb1;
        }
        __syncthreads();
    }

    // Epilogue: rows bm*64 + ty*8 + 2i (+1 in hi), cols tx*4..+3.
    const float LOG2E2 = 2.8853900817779268f;   // 2*log2(e)
#pragma unroll
    for (int i = 0; i < 4; i++) {
        float lo[4], hi[4];
#pragma unroll
        for (int j = 0; j < 4; j++) unpack2(acc2[i][j], lo[j], hi[j]);
        size_t r0 = (size_t)(bm * BM + ty * 8 + 2 * i) * H_ + tx * 4;
        if (tx < 16) {
            *(float4*)(Y + r0)      = make_float4(lo[0], lo[1], lo[2], lo[3]);
            *(float4*)(Y + r0 + H_) = make_float4(hi[0], hi[1], hi[2], hi[3]);
        } else {
            float4 el = make_float4(
                fast_ex2(lo[0] * LOG2E2), fast_ex2(lo[1] * LOG2E2),
                fast_ex2(lo[2] * LOG2E2), fast_ex2(lo[3] * LOG2E2));
            float4 eh = make_float4(
                fast_ex2(hi[0] * LOG2E2), fast_ex2(hi[1] * LOG2E2),
                fast_ex2(hi[2] * LOG2E2), fast_ex2(hi[3] * LOG2E2));
            *(float4*)(E + r0)      = el;
            *(float4*)(E + r0 + H_) = eh;
        }
    }
}

// ---------------------------------------------------------------------------
// Score kernel (R12 verbatim, 55.9us): 64/64 dual-pipe, interleaved.
// ---------------------------------------------------------------------------
#define TQ 32
#define TK 64
#define SR 66
#define OFF_QR 0
#define OFF_KR (OFF_QR + TQ * SR)
#define OFF_QE (OFF_KR + TK * SR)
#define OFF_KE (OFF_QE + TQ * SR)
#define OFF_WV (OFF_KE + TK * SR)
#define SMEM_FLOATS (OFF_WV + H_)          // 12800 -> 51200 bytes

__global__ __launch_bounds__(256) void score_kernel(
    const float* __restrict__ wv, float* __restrict__ out)
{
    extern __shared__ float sm[];
    float* qr  = sm + OFF_QR;
    float* kr  = sm + OFF_KR;
    float* qe  = sm + OFF_QE;
    float* ke  = sm + OFF_KE;
    float* swv = sm + OFF_WV;

    int b  = blockIdx.z;
    int q0 = blockIdx.y * TQ;
    int k0 = blockIdx.x * TK;

    int tid = threadIdx.x;
    int tx = tid & 15;
    int ty = tid >> 4;

    if (tid < H_) swv[tid] = wv[tid];

    const size_t qoff = (size_t)(b * LQ_ + q0) * H_;
    const size_t koff = (size_t)(b * LK_ + k0) * H_;

    for (int i = tid; i < TQ * 16; i += 256) {
        int r = i >> 4, c = i & 15;
        float4 v = *(const float4*)(g_Q + qoff + r * H_ + c * 4);
        float* d = &qr[r * SR + c * 4];
        *(float2*)(d)     = make_float2(v.x, v.y);
        *(float2*)(d + 2) = make_float2(v.z, v.w);
        float4 e = *(const float4*)(g_EQ + qoff + r * H_ + NTANH + c * 4);
        float* de = &qe[r * SR + c * 4];
        *(float2*)(de)     = make_float2(e.x, e.y);
        *(float2*)(de + 2) = make_float2(e.z, e.w);
    }
    for (int i = tid; i < TK * 16; i += 256) {
        int r = i >> 4, c = i & 15;
        float4 v = *(const float4*)(g_K + koff + r * H_ + c * 4);
        float* d = &kr[r * SR + c * 4];
        *(float2*)(d)     = make_float2(v.x, v.y);
        *(float2*)(d + 2) = make_float2(v.z, v.w);
        float4 e = *(const float4*)(g_EK + koff + r * H_ + NTANH + c * 4);
        float* de = &ke[r * SR + c * 4];
        *(float2*)(de)     = make_float2(e.x, e.y);
        *(float2*)(de + 2) = make_float2(e.z, e.w);
    }
    __syncthreads();

    ull accA[2][4];
    ull accB[2][4];
#pragma unroll
    for (int i = 0; i < 2; i++)
#pragma unroll
        for (int j = 0; j < 4; j++) { accA[i][j] = 0ull; accB[i][j] = 0ull; }

    const ull TWO2 = pack2(2.0f, 2.0f);
    const ull ONE2 = pack2(1.0f, 1.0f);
    const float* qr0 = qr + ty * SR;
    const float* kr0 = kr + tx * SR;
    const float* qe0 = qe + ty * SR;
    const float* ke0 = ke + tx * SR;

    for (int it = 0; it < 8; ++it) {
#pragma unroll
        for (int pp = 0; pp < 4; ++pp) {
            int p = it * 4 + pp;
            ull w2 = *(const ull*)(&swv[2 * p]);
            ull q2[2], k2[4];
            q2[0] = *(const ull*)(&qr0[2 * p]);
            q2[1] = *(const ull*)(&qr0[16 * SR + 2 * p]);
            k2[0] = *(const ull*)(&kr0[2 * p]);
            k2[1] = *(const ull*)(&kr0[16 * SR + 2 * p]);
            k2[2] = *(const ull*)(&kr0[32 * SR + 2 * p]);
            k2[3] = *(const ull*)(&kr0[48 * SR + 2 * p]);
#pragma unroll
            for (int i = 0; i < 2; i++)
#pragma unroll
                for (int j = 0; j < 4; j++) {
                    ull s = add2_(q2[i], k2[j]);
                    float sx, sy;
                    unpack2(s, sx, sy);
                    ull t = pack2(fast_tanh(sx), fast_tanh(sy));
                    accA[i][j] = fma2_(w2, t, accA[i][j]);
                }
        }
#pragma unroll
        for (int pp = 0; pp < 4; ++pp) {
            int p = it * 4 + pp;
            ull w2 = *(const ull*)(&swv[NTANH + 2 * p]);
            ull Eq2[2], Ek2[4];
            Eq2[0] = *(const ull*)(&qe0[2 * p]);
            Eq2[1] = *(const ull*)(&qe0[16 * SR + 2 * p]);
            Ek2[0] = *(const ull*)(&ke0[2 * p]);
            Ek2[1] = *(const ull*)(&ke0[16 * SR + 2 * p]);
            Ek2[2] = *(const ull*)(&ke0[32 * SR + 2 * p]);
            Ek2[3] = *(const ull*)(&ke0[48 * SR + 2 * p]);
#pragma unroll
            for (int i = 0; i < 2; i++)
#pragma unroll
                for (int j = 0; j < 4; j++) {
                    ull d = fma2_(Eq2[i], Ek2[j], ONE2);
                    float dx, dy;
                    unpack2(d, dx, dy);
                    float mx = __uint_as_float(0xFEF311C3u - __float_as_uint(dx));
                    float my = __uint_as_float(0xFEF311C3u - __float_as_uint(dy));
                    ull m = pack2(mx, my);
                    ull u = fma2_(d, m, TWO2);
                    m = mul2_(m, u);
                    u = fma2_(d, m, TWO2);
                    m = mul2_(m, u);
                    accB[i][j] = fma2_(w2, m, accB[i][j]);
                }
        }
    }

    float ws = 0.f;
#pragma unroll
    for (int h = NTANH; h < H_; ++h) ws += swv[h];

    float* ob = out + ((size_t)b * LQ_ + q0) * LK_ + k0;
#pragma unroll
    for (int i = 0; i < 2; i++)
#pragma unroll
        for (int j = 0; j < 4; j++) {
            float ax, ay, bx, by;
            unpack2(accA[i][j], ax, ay);
            unpack2(accB[i][j], bx, by);
            float val = (ax + ay) + ws + 2.0f * (bx + by);
            ob[(size_t)(ty + 16 * i) * LK_ + tx + 16 * j] = val;
        }
}

// ---------------------------------------------------------------------------

extern "C" void kernel_launch(void* const* d_in, const int* in_sizes, int n_in,
                              void* d_out, int out_size)
{
    const float* qs = (const float*)d_in[0];   // [8,512,512]
    const float* ks = (const float*)d_in[1];   // [8,512,512]
    const float* Wq = (const float*)d_in[2];   // [512,128]
    const float* Wk = (const float*)d_in[3];   // [512,128]
    const float* wv = (const float*)d_in[4];   // [128]
    float* out = (float*)d_out;                // [8,512,512]

    static int attr_set = 0;
    if (!attr_set) {
        cudaFuncSetAttribute(proj_kernel,
                             cudaFuncAttributeMaxDynamicSharedMemorySize,
                             P_SMEM_FLOATS * sizeof(float));
        cudaFuncSetAttribute(score_kernel,
                             cudaFuncAttributeMaxDynamicSharedMemorySize,
                             SMEM_FLOATS * sizeof(float));
        attr_set = 1;
    }

    proj_kernel<<<2 * (M_ / BM), 256, P_SMEM_FLOATS * sizeof(float)>>>(
        qs, ks, Wq, Wk);

    dim3 grid(LK_ / TK, LQ_ / TQ, B_);
    score_kernel<<<grid, 256, SMEM_FLOATS * sizeof(float)>>>(wv, out);
}